// round 1
// baseline (speedup 1.0000x reference)
#include <cuda_runtime.h>
#include <math.h>

#define NBALLS  256
#define BATCHN  128
#define NSTEPS  100
#define MAXEV   5
#define HID     64
#define P_PAIRS 32640          // 256*255/2
#define DTCONST 0.05f
#define WORLDSZ 10.0f

// ---------------- event log scratch (device globals; no allocation) ------------
__device__ int   g_type[NSTEPS * MAXEV];
__device__ int   g_ei  [NSTEPS * MAXEV];
__device__ int   g_ej  [NSTEPS * MAXEV];
__device__ float g_dte [NSTEPS * MAXEV];
__device__ float g_dtef[NSTEPS];

__constant__ float c_wnx[4] = { 1.f, -1.f, 0.f,  0.f };
__constant__ float c_wny[4] = { 0.f,  0.f, 1.f, -1.f };
__constant__ float c_wp [4] = { 0.f, -WORLDSZ, 0.f, -WORLDSZ };

__device__ __forceinline__ float silu_f(float x) {
    float s = 1.0f / (1.0f + expf(-x));
    return x * s;
}

// monotone float -> uint mapping (order-preserving incl. negatives)
__device__ __forceinline__ unsigned fkey(float f) {
    unsigned u = __float_as_uint(f);
    return (u & 0x80000000u) ? ~u : (u | 0x80000000u);
}
__device__ __forceinline__ float funkey(unsigned u) {
    u = (u & 0x80000000u) ? (u & 0x7FFFFFFFu) : ~u;
    return __uint_as_float(u);
}

// triu row offset: index of pair (i, i+1) in np.triu_indices(256, 1) ordering
__device__ __forceinline__ int triu_off(int i) {
    return i * 255 - ((i * (i - 1)) >> 1);
}

// ---------------- shared apply routines (identical code in both kernels) -------
// ball-ball jump via MLP; arrays are smem; tid mapping identical across kernels
__device__ void apply_jump(float* px, float* py, float* vx, float* vy,
                           int i, int j,
                           const float* sW1, const float* sb1,
                           const float* sW2, const float* sb2,
                           const float* sW3, float b3v,
                           float* h1, float* h2, int tid)
{
    float dx = px[j] - px[i];
    float dy = py[j] - py[i];
    float dist = sqrtf(__fmaf_rn(dx, dx, dy * dy));
    dist = fmaxf(dist, 1e-8f);
    float nhx = dx / dist, nhy = dy / dist;
    float app = __fmaf_rn(vx[j] - vx[i], nhx, (vy[j] - vy[i]) * nhy);

    if (tid < HID) {
        float z = __fmaf_rn(dist, sW1[2 * tid], __fmaf_rn(app, sW1[2 * tid + 1], sb1[tid]));
        h1[tid] = silu_f(z);
    }
    __syncthreads();
    if (tid < HID) {
        float acc = 0.0f;
        const float* row = sW2 + tid * HID;
#pragma unroll 8
        for (int m = 0; m < HID; m++) acc = __fmaf_rn(row[m], h1[m], acc);
        h2[tid] = silu_f(acc + sb2[tid]);
    }
    __syncthreads();
    if (tid == 0) {
        float acc = 0.0f;
        for (int m = 0; m < HID; m++) acc = __fmaf_rn(sW3[m], h2[m], acc);
        float imp = acc + b3v;
        float ix = imp * nhx, iy = imp * nhy;
        vx[i] += ix; vy[i] += iy;
        vx[j] -= ix; vy[j] -= iy;
    }
    __syncthreads();
}

// wall bounce (single-thread)
__device__ __forceinline__ void apply_wall1(float* px, float* py, float* vx, float* vy,
                                            int i, int w, float r)
{
    float wnx = c_wnx[w], wny = c_wny[w], wpv = c_wp[w];
    float v0 = vx[i], v1 = vy[i], p0 = px[i], p1 = py[i];
    float vn = __fmaf_rn(v0, wnx, v1 * wny);
    float t2 = 2.0f * vn;
    vx[i] = v0 - t2 * wnx;
    vy[i] = v1 - t2 * wny;
    float pn  = __fmaf_rn(p0, wnx, p1 * wny);
    float pen = fmaxf((wpv + r) - pn, 0.0f);
    px[i] = __fmaf_rn(pen, wnx, p0);
    py[i] = __fmaf_rn(pen, wny, p1);
}

// =============================== SCHEDULER =====================================
// One block simulates batch 0 and emits the global event log.
__global__ void __launch_bounds__(1024, 1)
sched_kernel(const float* __restrict__ state, const float* __restrict__ radii,
             const float* __restrict__ W1, const float* __restrict__ b1,
             const float* __restrict__ W2, const float* __restrict__ b2,
             const float* __restrict__ W3, const float* __restrict__ b3)
{
    __shared__ float s_px[NBALLS], s_py[NBALLS], s_vx[NBALLS], s_vy[NBALLS], s_r[NBALLS];
    __shared__ float sW1[2 * HID], sb1[HID], sW2[HID * HID], sb2[HID], sW3[HID];
    __shared__ float s_h1[HID], s_h2[HID];
    __shared__ unsigned long long red_k[32];
    __shared__ unsigned red_a[32];
    __shared__ unsigned long long s_bk;
    __shared__ unsigned s_ba;
    __shared__ int s_type, s_i, s_j, s_done;
    __shared__ float s_dte, s_tc, s_b3;

    int tid = threadIdx.x;

    for (int t = tid; t < NBALLS; t += 1024) {
        float4 v = ((const float4*)state)[t];   // batch 0 is the first 256 float4s
        s_px[t] = v.x; s_py[t] = v.y; s_vx[t] = v.z; s_vy[t] = v.w;
        s_r[t] = radii[t];
    }
    for (int t = tid; t < 2 * HID; t += 1024) sW1[t] = W1[t];
    for (int t = tid; t < HID; t += 1024) { sb1[t] = b1[t]; sb2[t] = b2[t]; sW3[t] = W3[t]; }
    for (int t = tid; t < HID * HID; t += 1024) sW2[t] = W2[t];
    if (tid == 0) s_b3 = b3[0];
    __syncthreads();

    const int ball  = tid & 255;
    const int chunk = tid >> 8;       // 0..3 -> which 32-wide d range

    for (int step = 0; step < NSTEPS; step++) {
        float t_s = (float)step * DTCONST;
        float t_e = t_s + DTCONST;
        if (tid == 0) { s_tc = t_s; s_done = 0; }
        if (tid < MAXEV) g_type[step * MAXEV + tid] = 0;
        __syncthreads();

        for (int ev = 0; ev < MAXEV; ev++) {
            if (s_done) break;

            // -------- detection: min over (approaching pairs with gap<=0.05) + walls
            unsigned long long bk = ~0ull;
            unsigned ba = 0u;
            float bpx = s_px[ball], bpy = s_py[ball];

            if (chunk == 0) {   // wall candidates for this ball
                float vx0 = s_vx[ball], vy0 = s_vy[ball], r = s_r[ball];
                float g[4];
                g[0] = bpx - r;
                g[1] = (WORLDSZ - bpx) - r;
                g[2] = bpy - r;
                g[3] = (WORLDSZ - bpy) - r;
                bool a[4] = { vx0 < 0.f, vx0 > 0.f, vy0 < 0.f, vy0 > 0.f };
                unsigned kb = (unsigned)(P_PAIRS + ball * 4);
#pragma unroll
                for (int w = 0; w < 4; w++) {
                    if (a[w]) {
                        unsigned long long key = (((unsigned long long)fkey(g[w])) << 32) | (kb + w);
                        if (key < bk) bk = key;
                    }
                }
            }

#pragma unroll 8
            for (int dd = 0; dd < 32; dd++) {
                int d = chunk * 32 + dd + 1;                 // 1..128
                if (d == 128 && ball >= 128) continue;       // avoid double-count
                int o = ball + d; if (o >= 256) o -= 256;
                float dx = s_px[o] - bpx;
                if (fabsf(dx) < 0.2502f) {
                    float dy = s_py[o] - bpy;
                    float d2 = __fmaf_rn(dx, dx, dy * dy);
                    if (d2 <= 0.06255f) {                    // dist <= ~0.25 (+margin)
                        int i, j;
                        if (o > ball) { i = ball; j = o; } else { i = o; j = ball; }
                        float dxp = s_px[j] - s_px[i];
                        float dyp = s_py[j] - s_py[i];
                        float dist = sqrtf(__fmaf_rn(dxp, dxp, dyp * dyp));
                        float den = dist + 1e-8f;
                        float ab  = __fmaf_rn(s_vx[j] - s_vx[i], dxp / den,
                                              (s_vy[j] - s_vy[i]) * (dyp / den));
                        if (ab < 0.0f) {
                            float gap = dist - (s_r[i] + s_r[j]);
                            unsigned kk = (unsigned)(triu_off(i) + (j - i - 1));
                            unsigned long long key = (((unsigned long long)fkey(gap)) << 32) | kk;
                            if (key < bk) { bk = key; ba = (unsigned)i; }
                        }
                    }
                }
            }

            // -------- block argmin reduction (key min; k in low bits => first-index tie-break)
#pragma unroll
            for (int off = 16; off; off >>= 1) {
                unsigned long long ok = __shfl_down_sync(0xffffffffu, bk, off);
                unsigned oa = __shfl_down_sync(0xffffffffu, ba, off);
                if (ok < bk) { bk = ok; ba = oa; }
            }
            int warp = tid >> 5, lane = tid & 31;
            if (lane == 0) { red_k[warp] = bk; red_a[warp] = ba; }
            __syncthreads();
            if (warp == 0) {
                bk = red_k[lane]; ba = red_a[lane];
#pragma unroll
                for (int off = 16; off; off >>= 1) {
                    unsigned long long ok = __shfl_down_sync(0xffffffffu, bk, off);
                    unsigned oa = __shfl_down_sync(0xffffffffu, ba, off);
                    if (ok < bk) { bk = ok; ba = oa; }
                }
                if (lane == 0) { s_bk = bk; s_ba = ba; }
            }
            __syncthreads();

            // -------- scalar event decision (thread 0)
            if (tid == 0) {
                int type = 0, ei = 0, ej = 0;
                float dte = 0.0f;
                unsigned long long best = s_bk;
                if (best != ~0ull) {
                    unsigned k = (unsigned)best;
                    float gap = funkey((unsigned)(best >> 32));
                    if (gap <= 0.05f) {
                        bool isball = (k < P_PAIRS);
                        float app;
                        if (isball) {
                            ei = (int)s_ba;
                            ej = (int)k - triu_off(ei) + ei + 1;
                            float nx = s_px[ej] - s_px[ei];
                            float ny = s_py[ej] - s_py[ei];
                            float nn = sqrtf(__fmaf_rn(nx, nx, ny * ny));
                            float ax = ((s_vx[ej] - s_vx[ei]) * nx) / nn;
                            float ay = ((s_vy[ej] - s_vy[ei]) * ny) / nn;
                            app = -(ax + ay);
                        } else {
                            int kw = (int)k - P_PAIRS;
                            ei = kw >> 2; ej = kw & 3;
                            app = fabsf(fmaxf(s_vx[ei], s_vy[ei]));
                        }
                        float t_ev = s_tc + gap / fmaxf(app, 1e-6f);
                        if (gap <= 0.0f) {
                            type = isball ? 1 : 3;           // case_a: apply at current state
                            dte = 0.0f;
                        } else if (app > 1e-6f && t_ev < t_e) {
                            type = isball ? 2 : 4;           // case_b: integrate dte, then apply
                            dte = (t_ev > s_tc + 1e-10f) ? (t_ev - s_tc) : 0.0f;
                            s_tc = t_ev;
                        } else {
                            s_done = 1;
                        }
                    } else s_done = 1;                        // no_event
                } else s_done = 1;                            // nothing approaching at all
                s_type = type; s_i = ei; s_j = ej; s_dte = dte;
                int idx = step * MAXEV + ev;
                g_type[idx] = type; g_ei[idx] = ei; g_ej[idx] = ej; g_dte[idx] = dte;
            }
            __syncthreads();

            // -------- apply to batch-0 smem state
            int ty = s_type;
            if (ty != 0) {
                if (ty == 2 || ty == 4) {                     // integrate positions by dte
                    if (tid < NBALLS) {
                        s_px[tid] = __fmaf_rn(s_vx[tid], s_dte, s_px[tid]);
                        s_py[tid] = __fmaf_rn(s_vy[tid], s_dte, s_py[tid]);
                    }
                    __syncthreads();
                }
                if (ty <= 2) {
                    apply_jump(s_px, s_py, s_vx, s_vy, s_i, s_j,
                               sW1, sb1, sW2, sb2, sW3, s_b3, s_h1, s_h2, tid);
                } else {
                    if (tid == 0) apply_wall1(s_px, s_py, s_vx, s_vy, s_i, s_j, s_r[s_i]);
                    __syncthreads();
                }
            }
        }

        // -------- end-of-step final integration to t_e
        __syncthreads();
        if (tid == 0) {
            float dtef = (t_e > s_tc + 1e-10f) ? (t_e - s_tc) : 0.0f;
            g_dtef[step] = dtef;
            s_dte = dtef;
        }
        __syncthreads();
        if (tid < NBALLS) {
            s_px[tid] = __fmaf_rn(s_vx[tid], s_dte, s_px[tid]);
            s_py[tid] = __fmaf_rn(s_vy[tid], s_dte, s_py[tid]);
        }
        __syncthreads();
    }
}

// =============================== WORKERS =======================================
// One block per batch; replays the event log; writes all 101 output frames.
__global__ void __launch_bounds__(256, 1)
worker_kernel(const float* __restrict__ state, const float* __restrict__ radii,
              const float* __restrict__ W1, const float* __restrict__ b1,
              const float* __restrict__ W2, const float* __restrict__ b2,
              const float* __restrict__ W3, const float* __restrict__ b3,
              float* __restrict__ out)
{
    __shared__ float s_px[NBALLS], s_py[NBALLS], s_vx[NBALLS], s_vy[NBALLS], s_r[NBALLS];
    __shared__ float sW1[2 * HID], sb1[HID], sW2[HID * HID], sb2[HID], sW3[HID];
    __shared__ float s_h1[HID], s_h2[HID];
    __shared__ float s_b3;
    __shared__ int   s_ty[MAXEV], s_ei[MAXEV], s_ej[MAXEV];
    __shared__ float s_dt[MAXEV], s_dtf;

    int tid = threadIdx.x;
    int b   = blockIdx.x;

    {
        float4 v = ((const float4*)(state + b * NBALLS * 4))[tid];
        s_px[tid] = v.x; s_py[tid] = v.y; s_vx[tid] = v.z; s_vy[tid] = v.w;
        s_r[tid] = radii[tid];
        ((float4*)out)[(size_t)b * NBALLS + tid] = v;    // frame 0 = initial state
    }
    for (int t = tid; t < 2 * HID; t += 256) sW1[t] = W1[t];
    for (int t = tid; t < HID; t += 256) { sb1[t] = b1[t]; sb2[t] = b2[t]; sW3[t] = W3[t]; }
    for (int t = tid; t < HID * HID; t += 256) sW2[t] = W2[t];
    if (tid == 0) s_b3 = b3[0];
    __syncthreads();

    for (int step = 0; step < NSTEPS; step++) {
        int base = step * MAXEV;
        if (tid < MAXEV) {
            s_ty[tid] = g_type[base + tid];
            s_ei[tid] = g_ei[base + tid];
            s_ej[tid] = g_ej[base + tid];
            s_dt[tid] = g_dte[base + tid];
        }
        if (tid == MAXEV) s_dtf = g_dtef[step];
        __syncthreads();

        for (int e = 0; e < MAXEV; e++) {
            int ty = s_ty[e];
            if (ty == 0) continue;
            if (ty == 2 || ty == 4) {
                s_px[tid] = __fmaf_rn(s_vx[tid], s_dt[e], s_px[tid]);
                s_py[tid] = __fmaf_rn(s_vy[tid], s_dt[e], s_py[tid]);
                __syncthreads();
            }
            if (ty <= 2) {
                apply_jump(s_px, s_py, s_vx, s_vy, s_ei[e], s_ej[e],
                           sW1, sb1, sW2, sb2, sW3, s_b3, s_h1, s_h2, tid);
            } else {
                if (tid == 0) apply_wall1(s_px, s_py, s_vx, s_vy, s_ei[e], s_ej[e], s_r[s_ei[e]]);
                __syncthreads();
            }
        }

        // final integration to t_e and frame write
        s_px[tid] = __fmaf_rn(s_vx[tid], s_dtf, s_px[tid]);
        s_py[tid] = __fmaf_rn(s_vy[tid], s_dtf, s_py[tid]);
        __syncthreads();
        float4 v = make_float4(s_px[tid], s_py[tid], s_vx[tid], s_vy[tid]);
        ((float4*)out)[((size_t)(step + 1) * BATCHN + b) * NBALLS + tid] = v;
        __syncthreads();   // protect s_ty reload next step
    }
}

// =============================== LAUNCH ========================================
extern "C" void kernel_launch(void* const* d_in, const int* in_sizes, int n_in,
                              void* d_out, int out_size)
{
    const float* state = (const float*)d_in[0];
    const float* radii = (const float*)d_in[1];
    const float* W1    = (const float*)d_in[2];
    const float* b1    = (const float*)d_in[3];
    const float* W2    = (const float*)d_in[4];
    const float* b2    = (const float*)d_in[5];
    const float* W3    = (const float*)d_in[6];
    const float* b3    = (const float*)d_in[7];
    float* out = (float*)d_out;

    sched_kernel<<<1, 1024>>>(state, radii, W1, b1, W2, b2, W3, b3);
    worker_kernel<<<BATCHN, 256>>>(state, radii, W1, b1, W2, b2, W3, b3, out);
}